// round 1
// baseline (speedup 1.0000x reference)
#include <cuda_runtime.h>

#define Hd 1024
#define Wd 1024
#define Bd 16

// Scratch: blurred grayscale field g [B,H,W], per-batch max(s) bits, gamma.
__device__ float d_g[(size_t)Bd * Hd * Wd];
__device__ unsigned int d_smax[Bd];
__device__ float d_gamma[Bd];

// Separable 1D Gaussian weights: g_i = exp(-0.5*ax^2/100), ax in {-2..2},
// w_i = g_i / sum(g). outer(w,w) == gaussian_kernel(5,10) exactly (real arith).
#define W0 0.19800304f
#define W1 0.20099548f
#define W2 0.20200297f

// ---------------------------------------------------------------------------
// K1: fused grayscale + 5x5 separable Gaussian blur (zero padding == 'SAME')
// Tile: 64 (W) x 32 (H) outputs, halo 2 each side. 256 threads.
// ---------------------------------------------------------------------------
#define TW 64
#define TH 32

__global__ void k_grayblur(const float* __restrict__ x,
                           const float* __restrict__ to_gray) {
    __shared__ float sgray[TH + 4][TW + 4];   // raw gray with halo
    __shared__ float shb[TH + 4][TW];         // after horizontal blur

    const int b  = blockIdx.z;
    const int i0 = blockIdx.y * TH;
    const int j0 = blockIdx.x * TW;
    const int t  = threadIdx.x;

    const float c0 = to_gray[0], c1 = to_gray[1], c2 = to_gray[2];
    const float* __restrict__ xr = x + (size_t)b * 3 * Hd * Wd;
    const float* __restrict__ xg = xr + (size_t)Hd * Wd;
    const float* __restrict__ xb = xg + (size_t)Hd * Wd;

    // Load gray tile with halo (zero outside image -> matches SAME zero pad)
    for (int idx = t; idx < (TH + 4) * (TW + 4); idx += 256) {
        int li = idx / (TW + 4), lj = idx % (TW + 4);
        int gi = i0 + li - 2, gj = j0 + lj - 2;
        float v = 0.0f;
        if (gi >= 0 && gi < Hd && gj >= 0 && gj < Wd) {
            size_t o = (size_t)gi * Wd + gj;
            v = c0 * __ldg(xr + o) + c1 * __ldg(xg + o) + c2 * __ldg(xb + o);
        }
        sgray[li][lj] = v;
    }
    __syncthreads();

    // Horizontal 5-tap
    for (int idx = t; idx < (TH + 4) * TW; idx += 256) {
        int li = idx / TW, lj = idx % TW;
        const float* r = &sgray[li][lj];
        shb[li][lj] = W0 * (r[0] + r[4]) + W1 * (r[1] + r[3]) + W2 * r[2];
    }
    __syncthreads();

    // Vertical 5-tap -> g
    float* __restrict__ gout = d_g + (size_t)b * Hd * Wd;
    for (int idx = t; idx < TH * TW; idx += 256) {
        int li = idx / TW, lj = idx % TW;
        float v = W0 * (shb[li][lj] + shb[li + 4][lj])
                + W1 * (shb[li + 1][lj] + shb[li + 3][lj])
                + W2 * shb[li + 2][lj];
        gout[(size_t)(i0 + li) * Wd + (j0 + lj)] = v;
    }
}

// ---------------------------------------------------------------------------
// jnp.gradient semantics: central interior, one-sided at edges.
// ---------------------------------------------------------------------------
__device__ __forceinline__ float gv(const float* __restrict__ gp, int i, int j) {
    return __ldg(gp + (size_t)i * Wd + j);
}
__device__ __forceinline__ float gradH(const float* __restrict__ gp, int i, int j) {
    if (i == 0)      return gv(gp, 1, j) - gv(gp, 0, j);
    if (i == Hd - 1) return gv(gp, Hd - 1, j) - gv(gp, Hd - 2, j);
    return 0.5f * (gv(gp, i + 1, j) - gv(gp, i - 1, j));
}
__device__ __forceinline__ float gradW(const float* __restrict__ gp, int i, int j) {
    if (j == 0)      return gv(gp, i, 1) - gv(gp, i, 0);
    if (j == Wd - 1) return gv(gp, i, Wd - 1) - gv(gp, i, Wd - 2);
    return 0.5f * (gv(gp, i, j + 1) - gv(gp, i, j - 1));
}
__device__ __forceinline__ void hess(const float* __restrict__ gp, int i, int j,
                                     float& h00, float& h01, float& h11) {
    // h00 = grad_H(grad_H(g))
    if (i == 0)           h00 = gradH(gp, 1, j) - gradH(gp, 0, j);
    else if (i == Hd - 1) h00 = gradH(gp, Hd - 1, j) - gradH(gp, Hd - 2, j);
    else                  h00 = 0.5f * (gradH(gp, i + 1, j) - gradH(gp, i - 1, j));
    // h01 = grad_W(grad_H(g))
    if (j == 0)           h01 = gradH(gp, i, 1) - gradH(gp, i, 0);
    else if (j == Wd - 1) h01 = gradH(gp, i, Wd - 1) - gradH(gp, i, Wd - 2);
    else                  h01 = 0.5f * (gradH(gp, i, j + 1) - gradH(gp, i, j - 1));
    // h11 = grad_W(grad_W(g))
    if (j == 0)           h11 = gradW(gp, i, 1) - gradW(gp, i, 0);
    else if (j == Wd - 1) h11 = gradW(gp, i, Wd - 1) - gradW(gp, i, Wd - 2);
    else                  h11 = 0.5f * (gradW(gp, i, j + 1) - gradW(gp, i, j - 1));
}
__device__ __forceinline__ float s_of(const float* __restrict__ gp, int i, int j) {
    float h00, h01, h11;
    hess(gp, i, j, h00, h01, h11);
    float mean = 0.5f * (h00 + h11);
    float diff = 0.5f * (h00 - h11);
    float disc = sqrtf(diff * diff + h01 * h01);
    float e0 = mean - disc, e1 = mean + disc;
    return sqrtf(e0 * e0 + e1 * e1);
}

// ---------------------------------------------------------------------------
// K_init: reset per-batch max bits
// ---------------------------------------------------------------------------
__global__ void k_init() {
    if (threadIdx.x < Bd) d_smax[threadIdx.x] = 0u;
}

// ---------------------------------------------------------------------------
// K2: per-batch max of s. Each block: 256 cols x 8 rows -> block reduce ->
// one atomicMax per block (s >= 0, so uint-bit ordering is monotonic).
// ---------------------------------------------------------------------------
__global__ void k_smax() {
    const int b = blockIdx.z;
    const int j = blockIdx.x * 256 + threadIdx.x;
    const int ibase = blockIdx.y * 8;
    const float* __restrict__ gp = d_g + (size_t)b * Hd * Wd;

    float m = 0.0f;
#pragma unroll
    for (int r = 0; r < 8; r++) {
        m = fmaxf(m, s_of(gp, ibase + r, j));
    }
    // warp reduce
#pragma unroll
    for (int o = 16; o > 0; o >>= 1)
        m = fmaxf(m, __shfl_xor_sync(0xffffffffu, m, o));

    __shared__ float wm[8];
    int lane = threadIdx.x & 31, wid = threadIdx.x >> 5;
    if (lane == 0) wm[wid] = m;
    __syncthreads();
    if (wid == 0) {
        m = (lane < 8) ? wm[lane] : 0.0f;
#pragma unroll
        for (int o = 4; o > 0; o >>= 1)
            m = fmaxf(m, __shfl_xor_sync(0xffffffffu, m, o));
        if (lane == 0)
            atomicMax(&d_smax[b], __float_as_uint(m));
    }
}

// ---------------------------------------------------------------------------
// K3: gamma = smax/2, with global all-zero -> 1.0 fallback
// ---------------------------------------------------------------------------
__global__ void k_gamma() {
    if (threadIdx.x == 0) {
        bool allz = true;
        for (int b = 0; b < Bd; b++)
            if (d_smax[b] != 0u) { allz = false; break; }
        for (int b = 0; b < Bd; b++)
            d_gamma[b] = allz ? 1.0f : 0.5f * __uint_as_float(d_smax[b]);
    }
}

// ---------------------------------------------------------------------------
// K4: final Frangi response
// ---------------------------------------------------------------------------
__global__ void k_final(float* __restrict__ out) {
    const int b = blockIdx.z;
    const int i = blockIdx.y;
    const int j = blockIdx.x * 256 + threadIdx.x;
    const float* __restrict__ gp = d_g + (size_t)b * Hd * Wd;

    float h00, h01, h11;
    hess(gp, i, j, h00, h01, h11);
    float mean = 0.5f * (h00 + h11);
    float diff = 0.5f * (h00 - h11);
    float disc = sqrtf(diff * diff + h01 * h01);
    float e0 = mean - disc, e1 = mean + disc;

    bool swap = fabsf(e1) < fabsf(e0);
    float lam1 = swap ? e1 : e0;
    float lam2 = fmaxf(swap ? e0 : e1, 1e-10f);
    float r_b = fabsf(lam1) / lam2;
    float s = sqrtf(e0 * e0 + e1 * e1);

    float gm = d_gamma[b];
    // exp(-r_b^2 / (2*BETA^2)) with BETA=0.5 -> exp(-2*r_b^2)
    float vals = expf(-2.0f * r_b * r_b)
               * (1.0f - expf(-(s * s) / (2.0f * gm * gm)));
    float f = fmaxf(0.0f, vals);
    out[((size_t)b * Hd + i) * Wd + j] = (f <= 0.0f) ? 1.0f : f;
}

// ---------------------------------------------------------------------------
extern "C" void kernel_launch(void* const* d_in, const int* in_sizes, int n_in,
                              void* d_out, int out_size) {
    const float* x  = (const float*)d_in[0];
    const float* tg = (const float*)d_in[1];
    if (n_in >= 2 && in_sizes[0] == 3) {  // defensive: order per metadata
        const float* tmp = x; x = tg; tg = tmp;
    }
    float* out = (float*)d_out;

    k_grayblur<<<dim3(Wd / TW, Hd / TH, Bd), 256>>>(x, tg);
    k_init<<<1, 32>>>();
    k_smax<<<dim3(Wd / 256, Hd / 8, Bd), 256>>>();
    k_gamma<<<1, 32>>>();
    k_final<<<dim3(Wd / 256, Hd, Bd), 256>>>(out);
}